// round 2
// baseline (speedup 1.0000x reference)
#include <cuda_runtime.h>
#include <cuda_bf16.h>
#include <cstdint>

// Problem constants (fixed by the reference)
#define F 26
#define D 128
#define NROWS 100000
#define B 4096
#define T (B * 20)

// One warp per (feature, bag). Lane l owns float4 chunk l of the 128-float row.
// D = 128 floats = 32 float4 -> exactly one float4 per lane, one fully
// coalesced 512B row read per gathered index.
// NOTE: indices/offsets are int32 on device (JAX x64 disabled downcasts int64).
__global__ __launch_bounds__(256) void ebag_pool_kernel(
    const float* __restrict__ tables,   // [F, NROWS, D]
    const int* __restrict__ values,     // [F, T]
    const int* __restrict__ offsets,    // [F, B+1]
    float* __restrict__ out)            // [B, F, D]
{
    const int lane = threadIdx.x & 31;
    const int warp = threadIdx.x >> 5;
    const int bag  = blockIdx.x * 8 + warp;     // 8 warps per block
    const int f    = blockIdx.y;
    if (bag >= B) return;

    const int* offs = offsets + (size_t)f * (B + 1);
    const int s = __ldg(offs + bag);
    const int e = __ldg(offs + bag + 1);

    const int* vals = values + (size_t)f * T;
    const float4* tab = reinterpret_cast<const float4*>(
        tables + (size_t)f * NROWS * D);

    float4 a0 = make_float4(0.f, 0.f, 0.f, 0.f);
    float4 a1 = make_float4(0.f, 0.f, 0.f, 0.f);
    float4 a2 = make_float4(0.f, 0.f, 0.f, 0.f);
    float4 a3 = make_float4(0.f, 0.f, 0.f, 0.f);

    int i = s;
    // Unroll x4 with independent accumulators -> MLP >= 4 on the gathers.
    for (; i + 4 <= e; i += 4) {
        int i0 = __ldg(vals + i + 0);
        int i1 = __ldg(vals + i + 1);
        int i2 = __ldg(vals + i + 2);
        int i3 = __ldg(vals + i + 3);
        float4 v0 = __ldg(tab + (size_t)i0 * 32 + lane);
        float4 v1 = __ldg(tab + (size_t)i1 * 32 + lane);
        float4 v2 = __ldg(tab + (size_t)i2 * 32 + lane);
        float4 v3 = __ldg(tab + (size_t)i3 * 32 + lane);
        a0.x += v0.x; a0.y += v0.y; a0.z += v0.z; a0.w += v0.w;
        a1.x += v1.x; a1.y += v1.y; a1.z += v1.z; a1.w += v1.w;
        a2.x += v2.x; a2.y += v2.y; a2.z += v2.z; a2.w += v2.w;
        a3.x += v3.x; a3.y += v3.y; a3.z += v3.z; a3.w += v3.w;
    }
    for (; i < e; ++i) {
        int i0 = __ldg(vals + i);
        float4 v0 = __ldg(tab + (size_t)i0 * 32 + lane);
        a0.x += v0.x; a0.y += v0.y; a0.z += v0.z; a0.w += v0.w;
    }

    float4 acc;
    acc.x = (a0.x + a1.x) + (a2.x + a3.x);
    acc.y = (a0.y + a1.y) + (a2.y + a3.y);
    acc.z = (a0.z + a1.z) + (a2.z + a3.z);
    acc.w = (a0.w + a1.w) + (a2.w + a3.w);

    // out[b][f][:] — always write (d_out is poisoned; empty bags must be 0)
    float4* o = reinterpret_cast<float4*>(out) + ((size_t)bag * F + f) * 32;
    o[lane] = acc;
}

extern "C" void kernel_launch(void* const* d_in, const int* in_sizes, int n_in,
                              void* d_out, int out_size) {
    const float* tables   = (const float*)d_in[0];
    const int*   values   = (const int*)d_in[1];
    const int*   offsets  = (const int*)d_in[2];
    float* out = (float*)d_out;

    dim3 grid(B / 8, F);   // feature on y: consecutive blocks share one table (L2 reuse)
    dim3 block(256);       // 8 warps = 8 bags per block
    ebag_pool_kernel<<<grid, block>>>(tables, values, offsets, out);
}